// round 17
// baseline (speedup 1.0000x reference)
#include <cuda_runtime.h>
#include <math.h>

// ReacPartialGbModel: B=4096 RK4 integrations, T=256 steps.
// R16 structure (1 elem/warp, weights in regs, 2 smem LUTs via
// A = 0.1*x0 + 1/6 + (2/3)*R, r3 software-pipelined, kof1 hoisted,
// all-butterfly reductions (q2/q3 packed 64-bit), no LUT clamps,
// ONE syncwarp/step) with history rings (xq, up) moved to per-warp smem
// (reads are off/medium-path uniform LDS; lane-0 writes; all same-step reads
// touch slots written >=1 step ago across a syncwarp) -> regs ~96 ->
// __launch_bounds__(128,5): 20 warps/SM, 1.38 waves.

namespace {

constexpr int kT = 256;
constexpr int kB = 4096;
constexpr int kN2 = 1024;              // LUT intervals over [-16,16)
constexpr float kH2    = 1.0f / 32.0f;
constexpr float kInvH2 = 32.0f;
constexpr float kSc    = 2.885390081777927f;  // 2*log2(e)

__device__ float2 g_nR[kN2 + 1];
__device__ float2 g_nB[kN2 + 1];
__device__ __align__(16) float4 g_lutR[kN2];
__device__ __align__(16) float4 g_lutB[kN2];

typedef unsigned long long ull;

// ---------------- helpers ---------------------------------------------------
__device__ __forceinline__ float tanh_acc(float x) {
    float ax = fabsf(x);
    float e  = __expf(-2.0f * ax);
    float r  = __fdividef(1.0f - e, 1.0f + e);
    return copysignf(r, x);
}
__device__ __forceinline__ float tanh_pre(float a) {   // input prescaled 2*log2e
    float e; asm("ex2.approx.f32 %0, %1;" : "=f"(e) : "f"(a));
    float s = e + 1.0f;
    float r; asm("rcp.approx.f32 %0, %1;" : "=f"(r) : "f"(s));
    return fmaf(-2.0f, r, 1.0f);
}
__device__ __forceinline__ ull fma2(ull a, ull b, ull c) {
    ull d; asm("fma.rn.f32x2 %0, %1, %2, %3;" : "=l"(d) : "l"(a), "l"(b), "l"(c));
    return d;
}
__device__ __forceinline__ ull add2(ull a, ull b) {
    ull d; asm("add.rn.f32x2 %0, %1, %2;" : "=l"(d) : "l"(a), "l"(b));
    return d;
}
__device__ __forceinline__ ull pk(float lo, float hi) {
    ull d; asm("mov.b64 %0, {%1, %2};" : "=l"(d) : "f"(lo), "f"(hi));
    return d;
}
__device__ __forceinline__ float upadd(ull v) {
    float lo, hi; asm("mov.b64 {%0, %1}, %2;" : "=f"(lo), "=f"(hi) : "l"(v));
    return lo + hi;
}

// ---------------- build kernel 1: one node per thread ------------------------
__global__ void build_nodes(const float* __restrict__ W0, const float* __restrict__ B0,
                            const float* __restrict__ W1, const float* __restrict__ B1,
                            const float* __restrict__ W2, const float* __restrict__ B2,
                            const float* __restrict__ V0, const float* __restrict__ C0,
                            const float* __restrict__ V1, const float* __restrict__ C1,
                            const float* __restrict__ V2, const float* __restrict__ C2)
{
    int idx = blockIdx.x * blockDim.x + threadIdx.x;
    if (idx >= 2 * (kN2 + 1)) return;
    int net  = idx / (kN2 + 1);
    int node = idx - net * (kN2 + 1);
    const float* w0 = net ? V0 : W0;  const float* b0 = net ? C0 : B0;
    const float* w1 = net ? V1 : W1;  const float* b1 = net ? C1 : B1;
    const float* w2 = net ? V2 : W2;  const float* b2 = net ? C2 : B2;

    float x = -16.0f + node * kH2;
    float t0[32], s0[32];
#pragma unroll
    for (int i = 0; i < 32; ++i) {
        float a  = fmaf(w0[i], x, b0[i]);
        float th = tanh_acc(a);
        t0[i] = th;
        s0[i] = (1.0f - th * th) * w0[i];
    }
    float y = b2[0], d = 0.0f;
    for (int j = 0; j < 32; ++j) {
        float a = b1[j], da = 0.0f;
#pragma unroll
        for (int i = 0; i < 32; ++i) {
            float w = w1[i * 32 + j];
            a  = fmaf(t0[i], w, a);
            da = fmaf(s0[i], w, da);
        }
        float th = tanh_acc(a);
        y = fmaf(w2[j], th, y);
        d = fmaf(w2[j] * (1.0f - th * th), da, d);
    }
    if (net == 0) {
        g_nR[node] = make_float2(1.5f * y, 1.5f * d);     // R = r1/0.2
    } else {
        g_nB[node] = make_float2((0.1f * fmaf(0.2f, x, 0.5f) + 0.6f * y) * 5.0f,
                                 (0.02f + 0.6f * d) * 5.0f);
    }
}

// ---------------- build kernel 2: Hermite -> cubic coefficients --------------
__device__ __forceinline__ float4 hermite2(float2 n0, float2 n1) {
    float hd0 = kH2 * n0.y, hd1 = kH2 * n1.y;
    float dy  = n1.x - n0.x;
    return make_float4(n0.x, hd0,
                       3.0f * dy - 2.0f * hd0 - hd1,
                       -2.0f * dy + hd0 + hd1);
}

__global__ void build_coeffs()
{
    int i = blockIdx.x * blockDim.x + threadIdx.x;
    if (i >= kN2) return;
    g_lutR[i] = hermite2(g_nR[i], g_nR[i + 1]);
    g_lutB[i] = hermite2(g_nB[i], g_nB[i + 1]);
}

// ---------------- main kernel ------------------------------------------------
// smem floats: [bufs 4x192][rings 4x32][lutR 1024 f4][lutB 1024 f4]
constexpr int kBufFloats  = 4 * 192;                   // 768
constexpr int kRingFloats = 4 * 32;                    // 128
constexpr int kSmemBytes  = (kBufFloats + kRingFloats) * 4 + 2 * kN2 * 16;  // 36352

__global__ void __launch_bounds__(128, 5)
rk4_kernel(const float* __restrict__ useq, const float* __restrict__ xz0,
           const float* __restrict__ r3W0, const float* __restrict__ r3b0,
           const float* __restrict__ r3W1, const float* __restrict__ r3b1,
           const float* __restrict__ r3W2, const float* __restrict__ r3b2,
           float* __restrict__ out)
{
    extern __shared__ __align__(16) float smemraw[];
    const int wslot = threadIdx.x >> 5;
    const int wid   = blockIdx.x * 4 + wslot;
    const int lane  = threadIdx.x & 31;

    float*  swarp = smemraw + wslot * 192;             // 2x96 h-parity
    float*  ring  = smemraw + kBufFloats + wslot * 32; // xq: 16f (8 ull), up: 8f
    ull*    xqs   = reinterpret_cast<ull*>(ring);
    float*  ups   = ring + 16;
    float4* sR    = reinterpret_cast<float4*>(smemraw + kBufFloats + kRingFloats);
    float4* sB    = sR + kN2;

    // ---- copy LUTs into shared memory --------------------------------------
    for (int k = threadIdx.x; k < kN2; k += 128) {
        sR[k] = __ldg(&g_lutR[k]);
        sB[k] = __ldg(&g_lutB[k]);
    }
    __syncthreads();

    // ---- weights in registers (critical chain), prescaled 2*log2e ----------
    ull w30p[8], w31p[16];
    float wu[8];
#pragma unroll
    for (int j = 0; j < 8; ++j)
        w30p[j] = pk(r3W0[(2 * j) * 32 + lane] * kSc,
                     r3W0[(2 * j + 1) * 32 + lane] * kSc);
#pragma unroll
    for (int k = 0; k < 8; ++k) wu[k] = r3W0[(16 + k) * 32 + lane] * kSc;
#pragma unroll
    for (int j = 0; j < 16; ++j)
        w31p[j] = pk(r3W1[(2 * j) * 32 + lane] * kSc,
                     r3W1[(2 * j + 1) * 32 + lane] * kSc);
    const float b30s = r3b0[lane] * kSc;
    const ull   b31p = pk(r3b1[lane] * kSc, 0.0f);
    const float w32  = r3W2[lane], b32 = r3b2[0];

    // ---- state: x in regs, history rings in per-warp smem --------------------
    const float* xz = xz0 + wid * 26;
    float x0 = xz[0], x1 = xz[1];
    if (lane == 0) {
#pragma unroll
        for (int j = 0; j < 8; ++j) xqs[j] = pk(xz[2 + 2 * j], xz[3 + 2 * j]);
#pragma unroll
        for (int k = 0; k < 8; ++k) ups[k] = xz[18 + k];
    }
    __syncwarp();

    const float4* uptr4 = reinterpret_cast<const float4*>(useq + wid * kT);
    float2* outp = reinterpret_cast<float2*>(out) + wid * kT;

    // no clamps: states provably interior to [-16,16)
    auto kof = [&](float x0v, float x1v, float r3s, float cafc,
                   float& k0, float& k1v) {
        float xf0 = fmaf(x0v, kInvH2, 512.0f);
        float f0  = floorf(xf0);
        float t0  = xf0 - f0;
        float4 cR = sR[(int)f0];
        float xf1 = fmaf(x1v, kInvH2, 512.0f);
        float f1  = floorf(xf1);
        float t1  = xf1 - f1;
        float4 cB = sB[(int)f1];
        float Rv = fmaf(fmaf(fmaf(cR.w, t0, cR.z), t0, cR.y), t0, cR.x);
        float Bv = fmaf(fmaf(fmaf(cB.w, t1, cB.z), t1, cB.y), t1, cB.x);
        k0  = fmaf(-2.0f / 3.0f, Rv, fmaf(-0.1f, x0v, cafc));
        k1v = (Rv - Bv) + r3s;
    };

    // ---- pipeline bootstrap (step 0, ring phase p=0) ------------------------
    float S1s, Uc, r3s1;
    {
        ull S1 = 0ull;
#pragma unroll
        for (int j = 0; j < 8; ++j) S1 = fma2(xqs[j], w30p[j], S1);
        float Ua = b30s, Ub = 0.0f;
#pragma unroll
        for (int k = 0; k < 8; k += 2) {
            Ua = fmaf(ups[k],     wu[k],     Ua);
            Ub = fmaf(ups[k + 1], wu[k + 1], Ub);
        }
        S1s = upadd(S1);
        Uc  = Ua + Ub;
        swarp[lane] = tanh_pre(S1s + Uc);
        __syncwarp();
        ull C = b31p;
        const ulonglong2* bq = reinterpret_cast<const ulonglong2*>(swarp);
#pragma unroll
        for (int q = 0; q < 8; ++q) {
            ulonglong2 v = bq[q];
            C = fma2(v.x, w31p[2 * q],     C);
            C = fma2(v.y, w31p[2 * q + 1], C);
        }
        __syncwarp();
        float q1b = tanh_pre(upadd(C)) * w32;
#pragma unroll
        for (int m = 16; m > 0; m >>= 1)
            q1b += __shfl_xor_sync(0xffffffffu, q1b, m);
        r3s1 = q1b + b32;
    }
    ull S4p = 0ull;
#pragma unroll
    for (int j = 0; j < 7; ++j) S4p = fma2(xqs[(1 + j) & 7], w30p[j], S4p);

#pragma unroll 1
    for (int tb = 0; tb < kT; tb += 8) {
        float4 ua = __ldg(uptr4 + (tb >> 2));
        float4 ub = __ldg(uptr4 + (tb >> 2) + 1);
        float uu[8] = {ua.x, ua.y, ua.z, ua.w, ub.x, ub.y, ub.z, ub.w};

#pragma unroll
        for (int p = 0; p < 8; ++p) {
            const float u = uu[p];
            const ull px = pk(x0, x1);
            if (lane == 0) {
                outp[tb + p] = make_float2(x0, x1);
                xqs[p & 7] = px;       // slot p: same-step reads use px reg
                ups[p & 7] = u;
            }
            const float cafc = fmaf(u, 1.0f / 6.0f, 1.0f / 6.0f);

            // ---- kof stage 1 HOISTED: needs only carried r3s1 + x ----------
            float k10, k11;
            kof(x0, x1, r3s1, cafc, k10, k11);
            float xb0 = fmaf(0.5f, k10, x0), xb1 = fmaf(0.5f, k11, x1);

            // ---- fast a3 computation -----------------------------------------
            float S4s = upadd(fma2(px, w30p[7], S4p));
            float a3_23 = fmaf(0.5f, S1s + S4s, Uc);
            float a3_4  = S4s + Uc;
            float Una = b30s, Unb = 0.0f;
#pragma unroll
            for (int k = 0; k < 6; k += 2) {
                Una = fmaf(ups[(p + 1 + k) & 7], wu[k],     Una);
                Unb = fmaf(ups[(p + 2 + k) & 7], wu[k + 1], Unb);
            }
            Una = fmaf(ups[(p + 7) & 7], wu[6], Una);
            Unb = fmaf(u, wu[7], Unb);
            float Un = Una + Unb;
            float a3_1n = S4s + Un;        // k1-stage preact for step t+1

            // ---- three p3 evals in one broadcast round ----------------------
            float h2  = tanh_pre(a3_23);
            float h3  = tanh_pre(a3_4);
            float h1n = tanh_pre(a3_1n);
            float* buf = swarp + (p & 1) * 96;
            buf[lane]      = h2;
            buf[32 + lane] = h3;
            buf[64 + lane] = h1n;
            __syncwarp();
            ull C2a = b31p, C2b = 0ull, C3a = b31p, C3b = 0ull,
                C1a = b31p, C1b = 0ull;
            const ulonglong2* bq = reinterpret_cast<const ulonglong2*>(buf);
#pragma unroll
            for (int q = 0; q < 8; ++q) {
                ulonglong2 v2 = bq[q];
                C2a = fma2(v2.x, w31p[2 * q],     C2a);
                C2b = fma2(v2.y, w31p[2 * q + 1], C2b);
                ulonglong2 v3 = bq[8 + q];
                C3a = fma2(v3.x, w31p[2 * q],     C3a);
                C3b = fma2(v3.y, w31p[2 * q + 1], C3b);
                ulonglong2 v1 = bq[16 + q];
                C1a = fma2(v1.x, w31p[2 * q],     C1a);
                C1b = fma2(v1.y, w31p[2 * q + 1], C1b);
            }
            // ---- reductions: q2+q3 packed 64-bit butterfly; q1 scalar -------
            float q2 = tanh_pre(upadd(add2(C2a, C2b))) * w32;
            float q3 = tanh_pre(upadd(add2(C3a, C3b))) * w32;
            float q1 = tanh_pre(upadd(add2(C1a, C1b))) * w32;
            ull q23 = pk(q2, q3);
#pragma unroll
            for (int m = 16; m > 0; m >>= 1) {
                q23 = add2(q23, __shfl_xor_sync(0xffffffffu, q23, m));
                q1 += __shfl_xor_sync(0xffffffffu, q1, m);
            }
            float q2s, q3s;
            asm("mov.b64 {%0, %1}, %2;" : "=f"(q2s), "=f"(q3s) : "l"(q23));
            float r3s23 = q2s + b32;
            float r3s4  = q3s + b32;
            float r3s1n = q1 + b32;

            // ---- RK4 k-chain (stage 1 already done) -------------------------
            float k20, k21; kof(xb0, xb1, r3s23, cafc, k20, k21);
            float xc0 = fmaf(0.5f, k20, x0), xc1 = fmaf(0.5f, k21, x1);
            float k30, k31; kof(xc0, xc1, r3s23, cafc, k30, k31);
            float xd0 = x0 + k30, xd1 = x1 + k31;
            float k40, k41; kof(xd0, xd1, r3s4, cafc, k40, k41);

            float nx0 = fmaf(k10 + 2.0f * (k20 + k30) + k40, 1.0f / 6.0f, x0);
            float nx1 = fmaf(k11 + 2.0f * (k21 + k31) + k41, 1.0f / 6.0f, x1);

            // ---- next-step S4 partial (smem ring reads, off-path) -----------
            // slots p+2..p+7 with w30p[0..5], plus px (newest) with w30p[6]
            ull S4n = 0ull;
#pragma unroll
            for (int j = 0; j < 6; ++j)
                S4n = fma2(xqs[(p + 2 + j) & 7], w30p[j], S4n);
            S4n = fma2(px, w30p[6], S4n);
            S4p = S4n;
            S1s = S4s;
            Uc  = Un;
            r3s1 = r3s1n;
            x0 = nx0; x1 = nx1;
        }
    }
}

}  // namespace

extern "C" void kernel_launch(void* const* d_in, const int* in_sizes, int n_in,
                              void* d_out, int out_size) {
    (void)in_sizes; (void)n_in; (void)out_size;
    const float* useq = (const float*)d_in[0];
    const float* xz0  = (const float*)d_in[1];
    const float* r1W0 = (const float*)d_in[2];
    const float* r1b0 = (const float*)d_in[3];
    const float* r1W1 = (const float*)d_in[4];
    const float* r1b1 = (const float*)d_in[5];
    const float* r1W2 = (const float*)d_in[6];
    const float* r1b2 = (const float*)d_in[7];
    const float* r2W0 = (const float*)d_in[8];
    const float* r2b0 = (const float*)d_in[9];
    const float* r2W1 = (const float*)d_in[10];
    const float* r2b1 = (const float*)d_in[11];
    const float* r2W2 = (const float*)d_in[12];
    const float* r2b2 = (const float*)d_in[13];
    const float* r3W0 = (const float*)d_in[14];
    const float* r3b0 = (const float*)d_in[15];
    const float* r3W1 = (const float*)d_in[16];
    const float* r3b1 = (const float*)d_in[17];
    const float* r3W2 = (const float*)d_in[18];
    const float* r3b2 = (const float*)d_in[19];
    float* out = (float*)d_out;

    cudaFuncSetAttribute(rk4_kernel, cudaFuncAttributeMaxDynamicSharedMemorySize,
                         kSmemBytes);

    build_nodes<<<(2 * (kN2 + 1) + 127) / 128, 128>>>(
        r1W0, r1b0, r1W1, r1b1, r1W2, r1b2,
        r2W0, r2b0, r2W1, r2b1, r2W2, r2b2);
    build_coeffs<<<(kN2 + 127) / 128, 128>>>();
    rk4_kernel<<<kB / 4, 128, kSmemBytes>>>(useq, xz0,
                                            r3W0, r3b0, r3W1, r3b1, r3W2, r3b2,
                                            out);
}